// round 3
// baseline (speedup 1.0000x reference)
#include <cuda_runtime.h>

#define N_NODES 65536
#define CF      16
#define L0      4097
#define SFC     2
#define LAT     128
#define HID     512
#define BATCH   16
#define KS      32
#define L1OUT   16385      // conv0 output length
#define NROWS   131104     // SPLIT * SFC = 16*4097*2

// -------- scratch (zero-init .bss, no runtime allocation) --------
__device__ float g_h1[HID * BATCH];                 // [512][16]  (k, b)
__device__ float g_a [SFC * CF * L0 * BATCH];       // [i][ci][l][b]
__device__ float g_c0[SFC * CF * L1OUT * BATCH];    // [i][ci][l][b]
__device__ float g_c1[SFC * N_NODES * BATCH];       // [i][o][b]

// packed dual-FMA: acc(2x f32) += w(2x f32) * x(2x f32)
__device__ __forceinline__ void dfma2(float2 &acc, float2 w, float2 x) {
    asm("{\n\t"
        ".reg .b64 a,b,c;\n\t"
        "mov.b64 a, {%2,%3};\n\t"
        "mov.b64 b, {%4,%5};\n\t"
        "mov.b64 c, {%0,%1};\n\t"
        "fma.rn.f32x2 c, a, b, c;\n\t"
        "mov.b64 {%0,%1}, c;\n\t"
        "}"
        : "+f"(acc.x), "+f"(acc.y)
        : "f"(w.x), "f"(w.y), "f"(x.x), "f"(x.y));
}

// ---------------- Stage 1: h1 = tanh(x @ W1^T + b1) ----------------
__global__ __launch_bounds__(256) void k_gemm1(
    const float* __restrict__ x, const float* __restrict__ W1,
    const float* __restrict__ b1)
{
    __shared__ float xs[BATCH * LAT];
    int tid = threadIdx.x;
    for (int t = tid; t < BATCH * LAT; t += 256) xs[t] = x[t];
    __syncthreads();

    int b = tid & 15;
    int j = blockIdx.x * 16 + (tid >> 4);
    const float4* w4 = (const float4*)(W1 + j * LAT);
    const float4* xv = (const float4*)(xs + b * LAT);
    float acc = 0.f;
#pragma unroll
    for (int c = 0; c < LAT / 4; c++) {
        float4 w = w4[c], xx = xv[c];
        acc += w.x * xx.x + w.y * xx.y + w.z * xx.z + w.w * xx.w;
    }
    g_h1[j * BATCH + b] = tanhf(acc + b1[j]);
}

// ---------------- Stage 2: h2 = tanh(h1 @ W2^T + b2) ----------------
// Shared-tiled: coalesced W2 loads into smem, padded-stride reads.
// Block: 256 thr = 128 rows x 2 batch-halves. Dynamic smem: hs + tile.
#define G2_R   128
#define G2_KT  128
#define G2_WS  (G2_KT + 4)            // 132-float row stride (16B aligned, low conflict)
#define G2_SMEM ((HID * BATCH + G2_R * G2_WS) * 4)

__global__ __launch_bounds__(256) void k_gemm2(
    const float* __restrict__ W2, const float* __restrict__ b2)
{
    extern __shared__ float dyn[];
    float* hs = dyn;                       // [512][16]
    float* ws = dyn + HID * BATCH;         // [128][132]

    int tid = threadIdx.x;
    {
        const float4* s4 = (const float4*)g_h1;
        float4* d4 = (float4*)hs;
#pragma unroll
        for (int t = 0; t < (HID * BATCH) / 4 / 256; t++)
            d4[tid + 256 * t] = s4[tid + 256 * t];
    }
    __syncthreads();

    int row_local = tid >> 1;
    int bh        = tid & 1;
    int row0      = blockIdx.x * G2_R;

    float2 acc[4];
#pragma unroll
    for (int p = 0; p < 4; p++) acc[p] = make_float2(0.f, 0.f);

    const float4* W4 = (const float4*)W2;
#pragma unroll 1
    for (int kt = 0; kt < HID / G2_KT; kt++) {
        // coalesced tile load: 128 rows x 32 float4
#pragma unroll
        for (int it = 0; it < 16; it++) {
            int e4 = tid + 256 * it;          // 0..4095
            int r  = e4 >> 5, c4 = e4 & 31;
            int gr = row0 + r; if (gr >= NROWS) gr = NROWS - 1;
            float4 v = W4[(size_t)gr * 128 + kt * 32 + c4];
            *(float4*)&ws[r * G2_WS + c4 * 4] = v;
        }
        __syncthreads();

        const float* wrow = &ws[row_local * G2_WS];
        const float4* hp4 = (const float4*)&hs[kt * G2_KT * BATCH + bh * 8];
#pragma unroll 8
        for (int k = 0; k < G2_KT; k++) {
            float w = wrow[k];
            float4 h0 = hp4[4 * k], h1 = hp4[4 * k + 1];
            float2 w2 = make_float2(w, w);
            dfma2(acc[0], w2, make_float2(h0.x, h0.y));
            dfma2(acc[1], w2, make_float2(h0.z, h0.w));
            dfma2(acc[2], w2, make_float2(h1.x, h1.y));
            dfma2(acc[3], w2, make_float2(h1.z, h1.w));
        }
        __syncthreads();
    }

    int r = row0 + row_local;
    if (r < NROWS) {
        float bias = b2[r];
        int i = r & 1, rem = r >> 1;
        int c = rem / L0, l = rem - c * L0;
        float* dst = &g_a[(size_t)(((i * CF + c) * L0) + l) * BATCH + bh * 8];
#pragma unroll
        for (int p = 0; p < 4; p++) {
            float2 v;
            v.x = tanhf(acc[p].x + bias);
            v.y = tanhf(acc[p].y + bias);
            *(float2*)(dst + 2 * p) = v;
        }
    }
}

// ---------------- Stage 3: ConvTranspose1d #0 (16->16, K=32, s=4, p=16, op=1) + tanh ----------------
__global__ __launch_bounds__(128) void k_conv0(
    const float* __restrict__ ctw0, const float* __restrict__ ctb0)
{
    int i   = blockIdx.y;
    int tid = threadIdx.x;
    __shared__ float ws[CF * CF * 33];
    for (int t = tid; t < CF * CF * KS; t += 128) {
        int ci = t >> 9, co = (t >> 5) & 15, k = t & 31;
        ws[(ci * 16 + co) * 33 + k] = ctw0[i * (CF * CF * KS) + t];
    }
    __syncthreads();

    int bp = tid & 7;
    int co = tid >> 3;
    int q0 = blockIdx.x * 4;

    float2 acc[4][4];
#pragma unroll
    for (int j = 0; j < 4; j++)
#pragma unroll
        for (int ph = 0; ph < 4; ph++) acc[j][ph] = make_float2(0.f, 0.f);

#pragma unroll 1
    for (int ci = 0; ci < CF; ci++) {
        const float* src = g_a + (size_t)((i * CF + ci) * L0) * BATCH + 2 * bp;
        float2 inv[11];
#pragma unroll
        for (int t = 0; t < 11; t++) {
            int l = q0 - 3 + t;
            inv[t] = (l >= 0 && l <= L0 - 1) ? *(const float2*)(src + (size_t)l * BATCH)
                                             : make_float2(0.f, 0.f);
        }
        const float* wsp = &ws[(ci * 16 + co) * 33];
        float wr[32];
#pragma unroll
        for (int k = 0; k < 32; k++) wr[k] = wsp[k];

#pragma unroll
        for (int s = 0; s < 8; s++)
#pragma unroll
            for (int ph = 0; ph < 4; ph++) {
                float2 w2 = make_float2(wr[ph + 4 * s], wr[ph + 4 * s]);
#pragma unroll
                for (int j = 0; j < 4; j++) dfma2(acc[j][ph], w2, inv[j + 7 - s]);
            }
    }

    float bias = ctb0[i * CF + co];
#pragma unroll
    for (int j = 0; j < 4; j++)
#pragma unroll
        for (int ph = 0; ph < 4; ph++) {
            int o = 4 * (q0 + j) + ph;
            if (o < L1OUT) {
                float2 v;
                v.x = tanhf(acc[j][ph].x + bias);
                v.y = tanhf(acc[j][ph].y + bias);
                *(float2*)&g_c0[(size_t)((i * CF + co) * L1OUT + o) * BATCH + 2 * bp] = v;
            }
        }
}

// ---------------- Stage 4: ConvTranspose1d #1 (16->1, K=32, s=4, p=16, op=0) + tanh ----------------
// 4 q per thread (doubled ILP, halved weight traffic)
__global__ __launch_bounds__(256) void k_conv1(
    const float* __restrict__ ctw1, const float* __restrict__ ctb1)
{
    int i   = blockIdx.y;
    int tid = threadIdx.x;
    __shared__ float wv[CF * KS];
    for (int t = tid; t < CF * KS; t += 256) wv[t] = ctw1[i * (CF * KS) + t];
    __syncthreads();

    int bp = tid & 7;
    int qi = tid >> 3;
    int q  = blockIdx.x * 128 + qi * 4;

    float2 acc[4][4];
#pragma unroll
    for (int j = 0; j < 4; j++)
#pragma unroll
        for (int ph = 0; ph < 4; ph++) acc[j][ph] = make_float2(0.f, 0.f);

#pragma unroll 1
    for (int ci = 0; ci < CF; ci++) {
        const float* src = g_c0 + (size_t)((i * CF + ci) * L1OUT) * BATCH + 2 * bp;
        float2 inv[11];
#pragma unroll
        for (int t = 0; t < 11; t++) {
            int l = q - 3 + t;
            inv[t] = (l >= 0 && l <= L1OUT - 1) ? *(const float2*)(src + (size_t)l * BATCH)
                                                : make_float2(0.f, 0.f);
        }
        const float* wp = &wv[ci * 32];
#pragma unroll
        for (int s = 0; s < 8; s++)
#pragma unroll
            for (int ph = 0; ph < 4; ph++) {
                float2 w2 = make_float2(wp[ph + 4 * s], wp[ph + 4 * s]);
#pragma unroll
                for (int j = 0; j < 4; j++) dfma2(acc[j][ph], w2, inv[j + 7 - s]);
            }
    }

    float bias = ctb1[i];
#pragma unroll
    for (int j = 0; j < 4; j++)
#pragma unroll
        for (int ph = 0; ph < 4; ph++) {
            int o = 4 * (q + j) + ph;          // exact: 128 blocks * 128 q = 16384
            float2 v;
            v.x = tanhf(acc[j][ph].x + bias);
            v.y = tanhf(acc[j][ph].y + bias);
            *(float2*)&g_c1[(size_t)(i * N_NODES + o) * BATCH + 2 * bp] = v;
        }
}

// ---------------- Stage 5: SFC gather + NN + final combine ----------------
// One block per 256-node tile; gather full 16-batch rows via 64B bursts once.
__global__ __launch_bounds__(256) void k_gather(
    const float* __restrict__ sps_w, const float* __restrict__ sps_b,
    const float* __restrict__ final_w, const float* __restrict__ final_b,
    const float* __restrict__ out_w, const float* __restrict__ out_b,
    const int* __restrict__ ord, float* __restrict__ out)
{
    __shared__ float gs[SFC][258][17];   // stride 17 -> conflict-free
    int tid = threadIdx.x;
    int n0  = blockIdx.x * 256;

    for (int t = tid; t < SFC * 258; t += 256) {
        int i  = (t >= 258);
        int tt = t - i * 258;
        int n  = n0 - 1 + tt;
        n = n < 0 ? 0 : (n > N_NODES - 1 ? N_NODES - 1 : n);
        int idx = ord[i * N_NODES + n];
        const float4* s4 = (const float4*)&g_c1[(size_t)(i * N_NODES + idx) * BATCH];
        float tmp[16];
        *(float4*)&tmp[0]  = s4[0];
        *(float4*)&tmp[4]  = s4[1];
        *(float4*)&tmp[8]  = s4[2];
        *(float4*)&tmp[12] = s4[3];
        float* row = gs[i][tt];
#pragma unroll
        for (int b = 0; b < 16; b++) row[b] = tmp[b];
    }
    __syncthreads();

    int n = n0 + tid;
    float w[SFC][3], sb[SFC];
#pragma unroll
    for (int i = 0; i < SFC; i++) {
        const float* wp = &sps_w[(size_t)(i * N_NODES + n) * 3];
        w[i][0] = wp[0]; w[i][1] = wp[1]; w[i][2] = wp[2];
        sb[i] = sps_b[i * N_NODES + n];
    }
    float fw0 = final_w[2 * n], fw1 = final_w[2 * n + 1];
    float fb = final_b[n], ow = out_w[n], ob = out_b[n];

#pragma unroll
    for (int b = 0; b < BATCH; b++) {
        float z0 = tanhf(gs[0][tid][b] * w[0][0] + gs[0][tid + 1][b] * w[0][1]
                       + gs[0][tid + 2][b] * w[0][2] + sb[0]);
        float z1 = tanhf(gs[1][tid][b] * w[1][0] + gs[1][tid + 1][b] * w[1][1]
                       + gs[1][tid + 2][b] * w[1][2] + sb[1]);
        float zz = tanhf(z0 * fw0 + z1 * fw1 + fb);
        out[(size_t)b * N_NODES + n] = zz * ow + ob;
    }
}

// ---------------- launch ----------------
extern "C" void kernel_launch(void* const* d_in, const int* in_sizes, int n_in,
                              void* d_out, int out_size)
{
    const float* x       = (const float*)d_in[0];
    const float* W1      = (const float*)d_in[1];
    const float* b1      = (const float*)d_in[2];
    const float* W2      = (const float*)d_in[3];
    const float* b2      = (const float*)d_in[4];
    const float* ctw0    = (const float*)d_in[5];
    const float* ctb0    = (const float*)d_in[6];
    const float* ctw1    = (const float*)d_in[7];
    const float* ctb1    = (const float*)d_in[8];
    const float* sps_w   = (const float*)d_in[9];
    const float* sps_b   = (const float*)d_in[10];
    const float* final_w = (const float*)d_in[11];
    const float* final_b = (const float*)d_in[12];
    const float* out_w   = (const float*)d_in[13];
    const float* out_b   = (const float*)d_in[14];
    const int*   ord     = (const int*)d_in[15];
    float* out = (float*)d_out;

    static int smem_set = 0;
    if (!smem_set) {
        cudaFuncSetAttribute(k_gemm2, cudaFuncAttributeMaxDynamicSharedMemorySize,
                             G2_SMEM);
        smem_set = 1;
    }

    k_gemm1<<<32, 256>>>(x, W1, b1);
    k_gemm2<<<(NROWS + G2_R - 1) / G2_R, 256, G2_SMEM>>>(W2, b2);
    k_conv0<<<dim3(1025, SFC), 128>>>(ctw0, ctb0);
    k_conv1<<<dim3(128, SFC), 256>>>(ctw1, ctb1);
    k_gather<<<dim3(256, 1), 256>>>(sps_w, sps_b, final_w, final_b,
                                    out_w, out_b, ord, out);
}

// round 4
// speedup vs baseline: 1.0802x; 1.0802x over previous
#include <cuda_runtime.h>

#define N_NODES 65536
#define CF      16
#define L0      4097
#define SFC     2
#define LAT     128
#define HID     512
#define BATCH   16
#define KS      32
#define L1OUT   16385      // conv0 output length
#define NROWS   131104     // SPLIT * SFC = 16*4097*2

// -------- scratch (zero-init .bss, no runtime allocation) --------
__device__ float g_h1[HID * BATCH];                 // [512][16]  (k, b)
__device__ float g_a [SFC * CF * L0 * BATCH];       // [i][ci][l][b]
__device__ float g_c0[SFC * CF * L1OUT * BATCH];    // [i][ci][l][b]
__device__ float g_c1[SFC * N_NODES * BATCH];       // [i][o][b]

// packed dual-FMA: acc(2x f32) += w(2x f32) * x(2x f32)
__device__ __forceinline__ void dfma2(float2 &acc, float2 w, float2 x) {
    asm("{\n\t"
        ".reg .b64 a,b,c;\n\t"
        "mov.b64 a, {%2,%3};\n\t"
        "mov.b64 b, {%4,%5};\n\t"
        "mov.b64 c, {%0,%1};\n\t"
        "fma.rn.f32x2 c, a, b, c;\n\t"
        "mov.b64 {%0,%1}, c;\n\t"
        "}"
        : "+f"(acc.x), "+f"(acc.y)
        : "f"(w.x), "f"(w.y), "f"(x.x), "f"(x.y));
}

// ---------------- Stage 1: h1 = tanh(x @ W1^T + b1) ----------------
__global__ __launch_bounds__(256) void k_gemm1(
    const float* __restrict__ x, const float* __restrict__ W1,
    const float* __restrict__ b1)
{
    __shared__ float xs[BATCH * LAT];
    int tid = threadIdx.x;
    for (int t = tid; t < BATCH * LAT; t += 256) xs[t] = x[t];
    __syncthreads();

    int b = tid & 15;
    int j = blockIdx.x * 16 + (tid >> 4);
    const float4* w4 = (const float4*)(W1 + j * LAT);
    const float4* xv = (const float4*)(xs + b * LAT);
    float acc = 0.f;
#pragma unroll
    for (int c = 0; c < LAT / 4; c++) {
        float4 w = w4[c], xx = xv[c];
        acc += w.x * xx.x + w.y * xx.y + w.z * xx.z + w.w * xx.w;
    }
    g_h1[j * BATCH + b] = tanhf(acc + b1[j]);
}

// ---------------- Stage 2: h2 = tanh(h1 @ W2^T + b2) ----------------
// Double-buffered tiles: 256 rows x 32 k. Thread = 4 rows x 4 batches.
// Tile layout ws[rg][k][j] (rg-stride 132 floats) -> conflict-free LDS.128.
#define G2_ROWS 256
#define G2_KT   32
#define G2_NKT  (HID / G2_KT)          // 16
#define G2_RGS  132                    // floats per rowgroup slab (32*4 + 4 pad)
#define G2_TILE (64 * G2_RGS)          // 64 rowgroups
#define G2_SMEM ((HID * BATCH + 2 * G2_TILE) * 4)   // 100352 B

__global__ __launch_bounds__(256) void k_gemm2(
    const float* __restrict__ W2, const float* __restrict__ b2)
{
    extern __shared__ float dyn[];
    float* hs = dyn;                    // [512][16]
    float* ws = dyn + HID * BATCH;      // [2][64][132]

    int tid  = threadIdx.x;
    int row0 = blockIdx.x * G2_ROWS;
    {
        const float4* s4 = (const float4*)g_h1;
        float4* d4 = (float4*)hs;
#pragma unroll
        for (int t = 0; t < (HID * BATCH) / 4 / 256; t++)
            d4[tid + 256 * t] = s4[tid + 256 * t];
    }

    const float4* W4 = (const float4*)W2;
    // loader mapping: 8 float4 per thread per tile; e4 -> (r = e4>>3, c4 = e4&7)
    int lr[8], lc4[8]; size_t goff[8];
#pragma unroll
    for (int m = 0; m < 8; m++) {
        int e4 = tid + 256 * m;
        lr[m]  = e4 >> 3;
        lc4[m] = e4 & 7;
        int gr = row0 + lr[m]; if (gr > NROWS - 1) gr = NROWS - 1;
        goff[m] = (size_t)gr * 128 + lc4[m];
    }

    // prologue: load tile 0
    float4 pf[8];
#pragma unroll
    for (int m = 0; m < 8; m++) pf[m] = W4[goff[m]];
#pragma unroll
    for (int m = 0; m < 8; m++) {
        int base = (lr[m] >> 2) * G2_RGS + (lr[m] & 3);
        ws[base + (4 * lc4[m] + 0) * 4] = pf[m].x;
        ws[base + (4 * lc4[m] + 1) * 4] = pf[m].y;
        ws[base + (4 * lc4[m] + 2) * 4] = pf[m].z;
        ws[base + (4 * lc4[m] + 3) * 4] = pf[m].w;
    }
    __syncthreads();

    int bq = tid & 3;          // batch quad: batches 4*bq..4*bq+3
    int rg = tid >> 2;         // rowgroup 0..63 (rows 4*rg..4*rg+3)

    float2 acc[4][2];
#pragma unroll
    for (int j = 0; j < 4; j++) { acc[j][0] = make_float2(0.f,0.f); acc[j][1] = make_float2(0.f,0.f); }

#pragma unroll 1
    for (int kt = 0; kt < G2_NKT; kt++) {
        int cur = kt & 1;
        if (kt + 1 < G2_NKT) {
#pragma unroll
            for (int m = 0; m < 8; m++) pf[m] = W4[goff[m] + (kt + 1) * 8];
        }
        const float4* wrow = (const float4*)&ws[cur * G2_TILE + rg * G2_RGS];
        const float4* hrow = (const float4*)&hs[kt * G2_KT * BATCH + bq * 4];
#pragma unroll 8
        for (int k = 0; k < G2_KT; k++) {
            float4 w = wrow[k];
            float4 h = hrow[4 * k];
            float2 hx = make_float2(h.x, h.y), hy = make_float2(h.z, h.w);
            dfma2(acc[0][0], make_float2(w.x, w.x), hx);
            dfma2(acc[0][1], make_float2(w.x, w.x), hy);
            dfma2(acc[1][0], make_float2(w.y, w.y), hx);
            dfma2(acc[1][1], make_float2(w.y, w.y), hy);
            dfma2(acc[2][0], make_float2(w.z, w.z), hx);
            dfma2(acc[2][1], make_float2(w.z, w.z), hy);
            dfma2(acc[3][0], make_float2(w.w, w.w), hx);
            dfma2(acc[3][1], make_float2(w.w, w.w), hy);
        }
        if (kt + 1 < G2_NKT) {
            int nxt = (kt + 1) & 1;
#pragma unroll
            for (int m = 0; m < 8; m++) {
                int base = nxt * G2_TILE + (lr[m] >> 2) * G2_RGS + (lr[m] & 3);
                ws[base + (4 * lc4[m] + 0) * 4] = pf[m].x;
                ws[base + (4 * lc4[m] + 1) * 4] = pf[m].y;
                ws[base + (4 * lc4[m] + 2) * 4] = pf[m].z;
                ws[base + (4 * lc4[m] + 3) * 4] = pf[m].w;
            }
        }
        __syncthreads();
    }

#pragma unroll
    for (int j = 0; j < 4; j++) {
        int r = row0 + 4 * rg + j;
        if (r < NROWS) {
            float bias = b2[r];
            int i = r & 1, rem = r >> 1;
            int c = rem / L0, l = rem - c * L0;
            float4 v;
            v.x = tanhf(acc[j][0].x + bias);
            v.y = tanhf(acc[j][0].y + bias);
            v.z = tanhf(acc[j][1].x + bias);
            v.w = tanhf(acc[j][1].y + bias);
            *(float4*)&g_a[(size_t)(((i * CF + c) * L0) + l) * BATCH + 4 * bq] = v;
        }
    }
}

// ---------------- Stage 3: ConvTranspose1d #0 (16->16, K=32, s=4, p=16, op=1) + tanh ----------------
__global__ __launch_bounds__(128) void k_conv0(
    const float* __restrict__ ctw0, const float* __restrict__ ctb0)
{
    int i   = blockIdx.y;
    int tid = threadIdx.x;
    __shared__ float ws[CF * CF * 33];
    for (int t = tid; t < CF * CF * KS; t += 128) {
        int ci = t >> 9, co = (t >> 5) & 15, k = t & 31;
        ws[(ci * 16 + co) * 33 + k] = ctw0[i * (CF * CF * KS) + t];
    }
    __syncthreads();

    int bp = tid & 7;
    int co = tid >> 3;
    int q0 = blockIdx.x * 4;

    float2 acc[4][4];
#pragma unroll
    for (int j = 0; j < 4; j++)
#pragma unroll
        for (int ph = 0; ph < 4; ph++) acc[j][ph] = make_float2(0.f, 0.f);

#pragma unroll 1
    for (int ci = 0; ci < CF; ci++) {
        const float* src = g_a + (size_t)((i * CF + ci) * L0) * BATCH + 2 * bp;
        float2 inv[11];
#pragma unroll
        for (int t = 0; t < 11; t++) {
            int l = q0 - 3 + t;
            inv[t] = (l >= 0 && l <= L0 - 1) ? *(const float2*)(src + (size_t)l * BATCH)
                                             : make_float2(0.f, 0.f);
        }
        const float* wsp = &ws[(ci * 16 + co) * 33];
#pragma unroll
        for (int s = 0; s < 8; s++)
#pragma unroll
            for (int ph = 0; ph < 4; ph++) {
                float wv = wsp[ph + 4 * s];
                float2 w2 = make_float2(wv, wv);
#pragma unroll
                for (int j = 0; j < 4; j++) dfma2(acc[j][ph], w2, inv[j + 7 - s]);
            }
    }

    float bias = ctb0[i * CF + co];
#pragma unroll
    for (int j = 0; j < 4; j++)
#pragma unroll
        for (int ph = 0; ph < 4; ph++) {
            int o = 4 * (q0 + j) + ph;
            if (o < L1OUT) {
                float2 v;
                v.x = tanhf(acc[j][ph].x + bias);
                v.y = tanhf(acc[j][ph].y + bias);
                *(float2*)&g_c0[(size_t)((i * CF + co) * L1OUT + o) * BATCH + 2 * bp] = v;
            }
        }
}

// ---------------- Stage 4: ConvTranspose1d #1 (16->1, K=32, s=4, p=16, op=0) + tanh ----------------
// 128 thr = 16 qi x 8 bp, 4 q per thread; 512 blocks for occupancy
__global__ __launch_bounds__(128) void k_conv1(
    const float* __restrict__ ctw1, const float* __restrict__ ctb1)
{
    int i   = blockIdx.y;
    int tid = threadIdx.x;
    __shared__ float wv[CF * KS];
    for (int t = tid; t < CF * KS; t += 128) wv[t] = ctw1[i * (CF * KS) + t];
    __syncthreads();

    int bp = tid & 7;
    int qi = tid >> 3;
    int q  = blockIdx.x * 64 + qi * 4;

    float2 acc[4][4];
#pragma unroll
    for (int j = 0; j < 4; j++)
#pragma unroll
        for (int ph = 0; ph < 4; ph++) acc[j][ph] = make_float2(0.f, 0.f);

#pragma unroll 1
    for (int ci = 0; ci < CF; ci++) {
        const float* src = g_c0 + (size_t)((i * CF + ci) * L1OUT) * BATCH + 2 * bp;
        float2 inv[11];
#pragma unroll
        for (int t = 0; t < 11; t++) {
            int l = q - 3 + t;
            inv[t] = (l >= 0 && l <= L1OUT - 1) ? *(const float2*)(src + (size_t)l * BATCH)
                                                : make_float2(0.f, 0.f);
        }
        const float* wp = &wv[ci * 32];
#pragma unroll
        for (int s = 0; s < 8; s++)
#pragma unroll
            for (int ph = 0; ph < 4; ph++) {
                float2 w2 = make_float2(wp[ph + 4 * s], wp[ph + 4 * s]);
#pragma unroll
                for (int j = 0; j < 4; j++) dfma2(acc[j][ph], w2, inv[j + 7 - s]);
            }
    }

    float bias = ctb1[i];
#pragma unroll
    for (int j = 0; j < 4; j++)
#pragma unroll
        for (int ph = 0; ph < 4; ph++) {
            int o = 4 * (q + j) + ph;          // 256 blocks * 64 q * 4 = 65536
            float2 v;
            v.x = tanhf(acc[j][ph].x + bias);
            v.y = tanhf(acc[j][ph].y + bias);
            *(float2*)&g_c1[(size_t)(i * N_NODES + o) * BATCH + 2 * bp] = v;
        }
}

// ---------------- Stage 5: SFC gather + NN + final combine ----------------
__global__ __launch_bounds__(256) void k_gather(
    const float* __restrict__ sps_w, const float* __restrict__ sps_b,
    const float* __restrict__ final_w, const float* __restrict__ final_b,
    const float* __restrict__ out_w, const float* __restrict__ out_b,
    const int* __restrict__ ord, float* __restrict__ out)
{
    __shared__ float gs[SFC][258][17];   // stride 17 -> conflict-free
    int tid = threadIdx.x;
    int n0  = blockIdx.x * 256;

    for (int t = tid; t < SFC * 258; t += 256) {
        int i  = (t >= 258);
        int tt = t - i * 258;
        int n  = n0 - 1 + tt;
        n = n < 0 ? 0 : (n > N_NODES - 1 ? N_NODES - 1 : n);
        int idx = ord[i * N_NODES + n];
        const float4* s4 = (const float4*)&g_c1[(size_t)(i * N_NODES + idx) * BATCH];
        float tmp[16];
        *(float4*)&tmp[0]  = s4[0];
        *(float4*)&tmp[4]  = s4[1];
        *(float4*)&tmp[8]  = s4[2];
        *(float4*)&tmp[12] = s4[3];
        float* row = gs[i][tt];
#pragma unroll
        for (int b = 0; b < 16; b++) row[b] = tmp[b];
    }
    __syncthreads();

    int n = n0 + tid;
    float w[SFC][3], sb[SFC];
#pragma unroll
    for (int i = 0; i < SFC; i++) {
        const float* wp = &sps_w[(size_t)(i * N_NODES + n) * 3];
        w[i][0] = wp[0]; w[i][1] = wp[1]; w[i][2] = wp[2];
        sb[i] = sps_b[i * N_NODES + n];
    }
    float fw0 = final_w[2 * n], fw1 = final_w[2 * n + 1];
    float fb = final_b[n], ow = out_w[n], ob = out_b[n];

#pragma unroll
    for (int b = 0; b < BATCH; b++) {
        float z0 = tanhf(gs[0][tid][b] * w[0][0] + gs[0][tid + 1][b] * w[0][1]
                       + gs[0][tid + 2][b] * w[0][2] + sb[0]);
        float z1 = tanhf(gs[1][tid][b] * w[1][0] + gs[1][tid + 1][b] * w[1][1]
                       + gs[1][tid + 2][b] * w[1][2] + sb[1]);
        float zz = tanhf(z0 * fw0 + z1 * fw1 + fb);
        out[(size_t)b * N_NODES + n] = zz * ow + ob;
    }
}

// ---------------- launch ----------------
extern "C" void kernel_launch(void* const* d_in, const int* in_sizes, int n_in,
                              void* d_out, int out_size)
{
    const float* x       = (const float*)d_in[0];
    const float* W1      = (const float*)d_in[1];
    const float* b1      = (const float*)d_in[2];
    const float* W2      = (const float*)d_in[3];
    const float* b2      = (const float*)d_in[4];
    const float* ctw0    = (const float*)d_in[5];
    const float* ctb0    = (const float*)d_in[6];
    const float* ctw1    = (const float*)d_in[7];
    const float* ctb1    = (const float*)d_in[8];
    const float* sps_w   = (const float*)d_in[9];
    const float* sps_b   = (const float*)d_in[10];
    const float* final_w = (const float*)d_in[11];
    const float* final_b = (const float*)d_in[12];
    const float* out_w   = (const float*)d_in[13];
    const float* out_b   = (const float*)d_in[14];
    const int*   ord     = (const int*)d_in[15];
    float* out = (float*)d_out;

    static int smem_set = 0;
    if (!smem_set) {
        cudaFuncSetAttribute(k_gemm2, cudaFuncAttributeMaxDynamicSharedMemorySize,
                             G2_SMEM);
        smem_set = 1;
    }

    k_gemm1<<<32, 256>>>(x, W1, b1);
    k_gemm2<<<(NROWS + G2_ROWS - 1) / G2_ROWS, 256, G2_SMEM>>>(W2, b2);
    k_conv0<<<dim3(1025, SFC), 128>>>(ctw0, ctb0);
    k_conv1<<<dim3(256, SFC), 128>>>(ctw1, ctb1);
    k_gather<<<dim3(256, 1), 256>>>(sps_w, sps_b, final_w, final_b,
                                    out_w, out_b, ord, out);
}

// round 5
// speedup vs baseline: 1.1771x; 1.0896x over previous
#include <cuda_runtime.h>

#define N_NODES 65536
#define CF      16
#define L0      4097
#define SFC     2
#define LAT     128
#define HID     512
#define BATCH   16
#define KS      32
#define L1OUT   16385      // conv0 output length
#define NROWS   131104     // SPLIT * SFC = 16*4097*2
#define HPAD    20         // padded batch stride for h (bank-conflict-free)

// -------- scratch (zero-init .bss, no runtime allocation) --------
__device__ float g_h1[HID * HPAD];                  // [512][20]  (k, b padded)
__device__ float g_a [SFC * CF * L0 * BATCH];       // [i][ci][l][b]
__device__ float g_c0[SFC * CF * L1OUT * BATCH];    // [i][ci][l][b]
__device__ float g_c1[SFC * N_NODES * BATCH];       // [i][o][b]

// packed dual-FMA: acc(2x f32) += w(2x f32) * x(2x f32)
__device__ __forceinline__ void dfma2(float2 &acc, float2 w, float2 x) {
    asm("{\n\t"
        ".reg .b64 a,b,c;\n\t"
        "mov.b64 a, {%2,%3};\n\t"
        "mov.b64 b, {%4,%5};\n\t"
        "mov.b64 c, {%0,%1};\n\t"
        "fma.rn.f32x2 c, a, b, c;\n\t"
        "mov.b64 {%0,%1}, c;\n\t"
        "}"
        : "+f"(acc.x), "+f"(acc.y)
        : "f"(w.x), "f"(w.y), "f"(x.x), "f"(x.y));
}

// ---------------- Stage 1: h1 = tanh(x @ W1^T + b1) ----------------
__global__ __launch_bounds__(256) void k_gemm1(
    const float* __restrict__ x, const float* __restrict__ W1,
    const float* __restrict__ b1)
{
    __shared__ float xs[BATCH * LAT];
    int tid = threadIdx.x;
    for (int t = tid; t < BATCH * LAT; t += 256) xs[t] = x[t];
    __syncthreads();

    int b = tid & 15;
    int j = blockIdx.x * 16 + (tid >> 4);
    const float4* w4 = (const float4*)(W1 + j * LAT);
    const float4* xv = (const float4*)(xs + b * LAT);
    float acc = 0.f;
#pragma unroll
    for (int c = 0; c < LAT / 4; c++) {
        float4 w = w4[c], xx = xv[c];
        acc += w.x * xx.x + w.y * xx.y + w.z * xx.z + w.w * xx.w;
    }
    g_h1[j * HPAD + b] = tanhf(acc + b1[j]);
}

// ---------------- Stage 2: h2 = tanh(h1 @ W2^T + b2) ----------------
// Warp = 8 rows x 8 k-groups. lane = c4*4 + rsub; thread: 2 rows, 64 k, 16 b.
// LDG.128 per warp-instr covers 8 rows x 128B contiguous (every line once).
// h in smem [512][20]; cross-lane k-reduction via shfl butterfly.
__global__ __launch_bounds__(256, 2) void k_gemm2(
    const float* __restrict__ W2, const float* __restrict__ b2)
{
    __shared__ float hs[HID * HPAD];    // 40 KB
    int tid = threadIdx.x;
    {
        const float4* s4 = (const float4*)g_h1;
        float4* d4 = (float4*)hs;
#pragma unroll
        for (int t = 0; t < (HID * HPAD) / 4 / 256; t++)
            d4[tid + 256 * t] = s4[tid + 256 * t];
    }
    __syncthreads();

    int lane = tid & 31, warp = tid >> 5;
    int c4 = lane >> 2, rsub = lane & 3;
    int r0 = blockIdx.x * 64 + warp * 8 + rsub * 2;       // rows r0, r0+1
    int rA = r0 < NROWS - 1 ? r0 : NROWS - 1;
    int rB = r0 + 1 < NROWS - 1 ? r0 + 1 : NROWS - 1;
    const float4* W4 = (const float4*)W2;
    size_t gA = (size_t)rA * 128 + c4;
    size_t gB = (size_t)rB * 128 + c4;

    float2 acc0[8], acc1[8];
#pragma unroll
    for (int p = 0; p < 8; p++) {
        acc0[p] = make_float2(0.f, 0.f);
        acc1[p] = make_float2(0.f, 0.f);
    }

#pragma unroll
    for (int j = 0; j < 16; j++) {
        float4 wA = W4[gA + 8 * j];
        float4 wB = W4[gB + 8 * j];
        int k0 = 4 * c4 + 32 * j;
        const float4* hp = (const float4*)(hs + k0 * HPAD);   // stride 5 float4 per k
#pragma unroll
        for (int kk = 0; kk < 4; kk++) {
            float4 h0 = hp[kk * 5 + 0];
            float4 h1 = hp[kk * 5 + 1];
            float4 h2 = hp[kk * 5 + 2];
            float4 h3 = hp[kk * 5 + 3];
            float wa = (kk == 0) ? wA.x : (kk == 1) ? wA.y : (kk == 2) ? wA.z : wA.w;
            float wb = (kk == 0) ? wB.x : (kk == 1) ? wB.y : (kk == 2) ? wB.z : wB.w;
            float2 w2a = make_float2(wa, wa);
            float2 w2b = make_float2(wb, wb);
            float2 hx0 = make_float2(h0.x, h0.y), hx1 = make_float2(h0.z, h0.w);
            float2 hx2 = make_float2(h1.x, h1.y), hx3 = make_float2(h1.z, h1.w);
            float2 hx4 = make_float2(h2.x, h2.y), hx5 = make_float2(h2.z, h2.w);
            float2 hx6 = make_float2(h3.x, h3.y), hx7 = make_float2(h3.z, h3.w);
            dfma2(acc0[0], w2a, hx0); dfma2(acc0[1], w2a, hx1);
            dfma2(acc0[2], w2a, hx2); dfma2(acc0[3], w2a, hx3);
            dfma2(acc0[4], w2a, hx4); dfma2(acc0[5], w2a, hx5);
            dfma2(acc0[6], w2a, hx6); dfma2(acc0[7], w2a, hx7);
            dfma2(acc1[0], w2b, hx0); dfma2(acc1[1], w2b, hx1);
            dfma2(acc1[2], w2b, hx2); dfma2(acc1[3], w2b, hx3);
            dfma2(acc1[4], w2b, hx4); dfma2(acc1[5], w2b, hx5);
            dfma2(acc1[6], w2b, hx6); dfma2(acc1[7], w2b, hx7);
        }
    }

    // reduce across c4 (lane bits 2..4)
#pragma unroll
    for (int m = 4; m <= 16; m <<= 1) {
#pragma unroll
        for (int p = 0; p < 8; p++) {
            acc0[p].x += __shfl_xor_sync(0xffffffffu, acc0[p].x, m);
            acc0[p].y += __shfl_xor_sync(0xffffffffu, acc0[p].y, m);
            acc1[p].x += __shfl_xor_sync(0xffffffffu, acc1[p].x, m);
            acc1[p].y += __shfl_xor_sync(0xffffffffu, acc1[p].y, m);
        }
    }

    // lane (c4) stores batch pair p = c4 for both rows
    float2 vA = acc0[0], vB = acc1[0];
#pragma unroll
    for (int p = 1; p < 8; p++)
        if (c4 == p) { vA = acc0[p]; vB = acc1[p]; }

    int b0 = 2 * c4;
    if (r0 < NROWS) {
        float bias = b2[r0];
        int i = r0 & 1, rem = r0 >> 1;
        int c = rem / L0, l = rem - c * L0;
        float2 o;
        o.x = tanhf(vA.x + bias);
        o.y = tanhf(vA.y + bias);
        *(float2*)&g_a[(size_t)((i * CF + c) * L0 + l) * BATCH + b0] = o;
    }
    if (r0 + 1 < NROWS) {
        int r = r0 + 1;
        float bias = b2[r];
        int i = r & 1, rem = r >> 1;
        int c = rem / L0, l = rem - c * L0;
        float2 o;
        o.x = tanhf(vB.x + bias);
        o.y = tanhf(vB.y + bias);
        *(float2*)&g_a[(size_t)((i * CF + c) * L0 + l) * BATCH + b0] = o;
    }
}

// ---------------- Stage 3: ConvTranspose1d #0 (16->16, K=32, s=4, p=16, op=1) + tanh ----------------
// software-pipelined over ci: prefetch inv for ci+1 before computing ci
__global__ __launch_bounds__(128) void k_conv0(
    const float* __restrict__ ctw0, const float* __restrict__ ctb0)
{
    int i   = blockIdx.y;
    int tid = threadIdx.x;
    __shared__ float ws[CF * CF * 33];
    for (int t = tid; t < CF * CF * KS; t += 128) {
        int ci = t >> 9, co = (t >> 5) & 15, k = t & 31;
        ws[(ci * 16 + co) * 33 + k] = ctw0[i * (CF * CF * KS) + t];
    }
    __syncthreads();

    int bp = tid & 7;
    int co = tid >> 3;
    int q0 = blockIdx.x * 4;

    float2 acc[4][4];
#pragma unroll
    for (int j = 0; j < 4; j++)
#pragma unroll
        for (int ph = 0; ph < 4; ph++) acc[j][ph] = make_float2(0.f, 0.f);

    float2 inv[2][11];
    {
        const float* src = g_a + (size_t)(i * CF * L0) * BATCH + 2 * bp;
#pragma unroll
        for (int t = 0; t < 11; t++) {
            int l = q0 - 3 + t;
            inv[0][t] = (l >= 0 && l <= L0 - 1) ? *(const float2*)(src + (size_t)l * BATCH)
                                                : make_float2(0.f, 0.f);
        }
    }

#pragma unroll
    for (int ci = 0; ci < CF; ci++) {
        int cur = ci & 1;
        if (ci + 1 < CF) {
            const float* src = g_a + (size_t)((i * CF + ci + 1) * L0) * BATCH + 2 * bp;
#pragma unroll
            for (int t = 0; t < 11; t++) {
                int l = q0 - 3 + t;
                inv[cur ^ 1][t] = (l >= 0 && l <= L0 - 1)
                    ? *(const float2*)(src + (size_t)l * BATCH) : make_float2(0.f, 0.f);
            }
        }
        const float* wsp = &ws[(ci * 16 + co) * 33];
#pragma unroll
        for (int s = 0; s < 8; s++)
#pragma unroll
            for (int ph = 0; ph < 4; ph++) {
                float wv = wsp[ph + 4 * s];
                float2 w2 = make_float2(wv, wv);
#pragma unroll
                for (int j = 0; j < 4; j++) dfma2(acc[j][ph], w2, inv[cur][j + 7 - s]);
            }
    }

    float bias = ctb0[i * CF + co];
#pragma unroll
    for (int j = 0; j < 4; j++)
#pragma unroll
        for (int ph = 0; ph < 4; ph++) {
            int o = 4 * (q0 + j) + ph;
            if (o < L1OUT) {
                float2 v;
                v.x = tanhf(acc[j][ph].x + bias);
                v.y = tanhf(acc[j][ph].y + bias);
                *(float2*)&g_c0[(size_t)((i * CF + co) * L1OUT + o) * BATCH + 2 * bp] = v;
            }
        }
}

// ---------------- Stage 4: ConvTranspose1d #1 (16->1, K=32, s=4, p=16, op=0) + tanh ----------------
// 2 q per thread, 1024 blocks, pipelined ci
__global__ __launch_bounds__(128) void k_conv1(
    const float* __restrict__ ctw1, const float* __restrict__ ctb1)
{
    int i   = blockIdx.y;
    int tid = threadIdx.x;
    __shared__ float wv[CF * KS];
    for (int t = tid; t < CF * KS; t += 128) wv[t] = ctw1[i * (CF * KS) + t];
    __syncthreads();

    int bp = tid & 7;
    int qi = tid >> 3;
    int q  = blockIdx.x * 32 + qi * 2;

    float2 acc[2][4];
#pragma unroll
    for (int j = 0; j < 2; j++)
#pragma unroll
        for (int ph = 0; ph < 4; ph++) acc[j][ph] = make_float2(0.f, 0.f);

    float2 inv[2][9];
    {
        const float* src = g_c0 + (size_t)(i * CF * L1OUT) * BATCH + 2 * bp;
#pragma unroll
        for (int t = 0; t < 9; t++) {
            int l = q - 3 + t;
            inv[0][t] = (l >= 0 && l <= L1OUT - 1) ? *(const float2*)(src + (size_t)l * BATCH)
                                                   : make_float2(0.f, 0.f);
        }
    }

#pragma unroll
    for (int ci = 0; ci < CF; ci++) {
        int cur = ci & 1;
        if (ci + 1 < CF) {
            const float* src = g_c0 + (size_t)((i * CF + ci + 1) * L1OUT) * BATCH + 2 * bp;
#pragma unroll
            for (int t = 0; t < 9; t++) {
                int l = q - 3 + t;
                inv[cur ^ 1][t] = (l >= 0 && l <= L1OUT - 1)
                    ? *(const float2*)(src + (size_t)l * BATCH) : make_float2(0.f, 0.f);
            }
        }
        const float* wp = &wv[ci * 32];
#pragma unroll
        for (int s = 0; s < 8; s++)
#pragma unroll
            for (int ph = 0; ph < 4; ph++) {
                float2 w2 = make_float2(wp[ph + 4 * s], wp[ph + 4 * s]);
                dfma2(acc[0][ph], w2, inv[cur][7 - s]);
                dfma2(acc[1][ph], w2, inv[cur][8 - s]);
            }
    }

    float bias = ctb1[i];
#pragma unroll
    for (int j = 0; j < 2; j++)
#pragma unroll
        for (int ph = 0; ph < 4; ph++) {
            int o = 4 * (q + j) + ph;
            float2 v;
            v.x = tanhf(acc[j][ph].x + bias);
            v.y = tanhf(acc[j][ph].y + bias);
            *(float2*)&g_c1[(size_t)(i * N_NODES + o) * BATCH + 2 * bp] = v;
        }
}

// ---------------- Stage 5: SFC gather + NN + final combine ----------------
__global__ __launch_bounds__(256) void k_gather(
    const float* __restrict__ sps_w, const float* __restrict__ sps_b,
    const float* __restrict__ final_w, const float* __restrict__ final_b,
    const float* __restrict__ out_w, const float* __restrict__ out_b,
    const int* __restrict__ ord, float* __restrict__ out)
{
    __shared__ float gs[SFC][258][17];   // stride 17 -> conflict-free
    int tid = threadIdx.x;
    int n0  = blockIdx.x * 256;

    for (int t = tid; t < SFC * 258; t += 256) {
        int i  = (t >= 258);
        int tt = t - i * 258;
        int n  = n0 - 1 + tt;
        n = n < 0 ? 0 : (n > N_NODES - 1 ? N_NODES - 1 : n);
        int idx = ord[i * N_NODES + n];
        const float4* s4 = (const float4*)&g_c1[(size_t)(i * N_NODES + idx) * BATCH];
        float tmp[16];
        *(float4*)&tmp[0]  = s4[0];
        *(float4*)&tmp[4]  = s4[1];
        *(float4*)&tmp[8]  = s4[2];
        *(float4*)&tmp[12] = s4[3];
        float* row = gs[i][tt];
#pragma unroll
        for (int b = 0; b < 16; b++) row[b] = tmp[b];
    }
    __syncthreads();

    int n = n0 + tid;
    float w[SFC][3], sb[SFC];
#pragma unroll
    for (int i = 0; i < SFC; i++) {
        const float* wp = &sps_w[(size_t)(i * N_NODES + n) * 3];
        w[i][0] = wp[0]; w[i][1] = wp[1]; w[i][2] = wp[2];
        sb[i] = sps_b[i * N_NODES + n];
    }
    float fw0 = final_w[2 * n], fw1 = final_w[2 * n + 1];
    float fb = final_b[n], ow = out_w[n], ob = out_b[n];

#pragma unroll
    for (int b = 0; b < BATCH; b++) {
        float z0 = tanhf(gs[0][tid][b] * w[0][0] + gs[0][tid + 1][b] * w[0][1]
                       + gs[0][tid + 2][b] * w[0][2] + sb[0]);
        float z1 = tanhf(gs[1][tid][b] * w[1][0] + gs[1][tid + 1][b] * w[1][1]
                       + gs[1][tid + 2][b] * w[1][2] + sb[1]);
        float zz = tanhf(z0 * fw0 + z1 * fw1 + fb);
        out[(size_t)b * N_NODES + n] = zz * ow + ob;
    }
}

// ---------------- launch ----------------
extern "C" void kernel_launch(void* const* d_in, const int* in_sizes, int n_in,
                              void* d_out, int out_size)
{
    const float* x       = (const float*)d_in[0];
    const float* W1      = (const float*)d_in[1];
    const float* b1      = (const float*)d_in[2];
    const float* W2      = (const float*)d_in[3];
    const float* b2      = (const float*)d_in[4];
    const float* ctw0    = (const float*)d_in[5];
    const float* ctb0    = (const float*)d_in[6];
    const float* ctw1    = (const float*)d_in[7];
    const float* ctb1    = (const float*)d_in[8];
    const float* sps_w   = (const float*)d_in[9];
    const float* sps_b   = (const float*)d_in[10];
    const float* final_w = (const float*)d_in[11];
    const float* final_b = (const float*)d_in[12];
    const float* out_w   = (const float*)d_in[13];
    const float* out_b   = (const float*)d_in[14];
    const int*   ord     = (const int*)d_in[15];
    float* out = (float*)d_out;

    k_gemm1<<<32, 256>>>(x, W1, b1);
    k_gemm2<<<(NROWS + 63) / 64, 256>>>(W2, b2);
    k_conv0<<<dim3(1025, SFC), 128>>>(ctw0, ctb0);
    k_conv1<<<dim3(512, SFC), 128>>>(ctw1, ctb1);
    k_gather<<<dim3(256, 1), 256>>>(sps_w, sps_b, final_w, final_b,
                                    out_w, out_b, ord, out);
}

// round 7
// speedup vs baseline: 1.2262x; 1.0417x over previous
#include <cuda_runtime.h>

#define N_NODES 65536
#define CF      16
#define L0      4097
#define SFC     2
#define LAT     128
#define HID     512
#define BATCH   16
#define KS      32
#define L1OUT   16385
#define NROWS   131104

// -------- scratch --------
__device__ float g_h1[HID * BATCH];                 // [512][16]
__device__ float g_a [SFC * CF * L0 * BATCH];       // [i][ci][l][b]
__device__ float g_c0[SFC * CF * L1OUT * BATCH];    // [i][ci][l][b]
__device__ float g_c1[SFC * N_NODES * BATCH];       // [i][o][b]

__device__ __forceinline__ void dfma2(float2 &acc, float2 w, float2 x) {
    asm("{\n\t"
        ".reg .b64 a,b,c;\n\t"
        "mov.b64 a, {%2,%3};\n\t"
        "mov.b64 b, {%4,%5};\n\t"
        "mov.b64 c, {%0,%1};\n\t"
        "fma.rn.f32x2 c, a, b, c;\n\t"
        "mov.b64 {%0,%1}, c;\n\t"
        "}"
        : "+f"(acc.x), "+f"(acc.y)
        : "f"(w.x), "f"(w.y), "f"(x.x), "f"(x.y));
}

__device__ __forceinline__ void cp_async16(void* smem, const void* gmem) {
    unsigned s = (unsigned)__cvta_generic_to_shared(smem);
    asm volatile("cp.async.cg.shared.global [%0], [%1], 16;" :: "r"(s), "l"(gmem));
}

// ---------------- Stage 1 ----------------
__global__ __launch_bounds__(256) void k_gemm1(
    const float* __restrict__ x, const float* __restrict__ W1,
    const float* __restrict__ b1)
{
    __shared__ float xs[BATCH * LAT];
    int tid = threadIdx.x;
    for (int t = tid; t < BATCH * LAT; t += 256) xs[t] = x[t];
    __syncthreads();

    int b = tid & 15;
    int j = blockIdx.x * 16 + (tid >> 4);
    const float4* w4 = (const float4*)(W1 + j * LAT);
    const float4* xv = (const float4*)(xs + b * LAT);
    float acc = 0.f;
#pragma unroll
    for (int c = 0; c < LAT / 4; c++) {
        float4 w = w4[c], xx = xv[c];
        acc += w.x * xx.x + w.y * xx.y + w.z * xx.z + w.w * xx.w;
    }
    g_h1[j * BATCH + b] = tanhf(acc + b1[j]);
}

// ---------------- Stage 2: cp.async-ring GEMM ----------------
// Block 256 = 8 warps x 8 rows = 64 rows. lane = c4(k-slice) + 8*rsub(batch-quad).
// h slots: hs4[(k>>2)*17 + (k&3)*4 + m] -> LDS.128 bank-group = c4 (conflict-free)
// W2 ring: 4 stages x [64 rows][9 float4]. One commit_group per iteration
// (empty groups allowed) so wait_group 2 always guarantees stage j complete.
#define G2_HS4   2176                  // 128*17 float4
#define G2_WT4   576                   // 64*9 float4 per stage
#define G2_SMEM  ((G2_HS4 + 4 * G2_WT4) * 16)   // 71680 B

__global__ __launch_bounds__(256) void k_gemm2(
    const float* __restrict__ W2, const float* __restrict__ b2)
{
    extern __shared__ float4 dyn4[];
    float4* hs4 = dyn4;
    float4* wt4 = dyn4 + G2_HS4;

    int tid  = threadIdx.x;
    int lane = tid & 31, warp = tid >> 5;
    int c4   = lane & 7, rsub = lane >> 3;
    int row0 = blockIdx.x * 64;

    // stage h into slotted layout
    for (int t = tid; t < 2048; t += 256) {
        int k = t >> 2, m = t & 3;
        float4 v = ((const float4*)g_h1)[t];
        hs4[(k >> 2) * 17 + (k & 3) * 4 + m] = v;
    }

    // loader offsets
    const float4* W4 = (const float4*)W2;
    size_t gbase[2]; int sslot[2];
#pragma unroll
    for (int m = 0; m < 2; m++) {
        int e = tid + 256 * m;
        int r = e >> 3, c = e & 7;
        int gr = row0 + r; if (gr > NROWS - 1) gr = NROWS - 1;
        gbase[m] = (size_t)gr * 128 + c;
        sslot[m] = r * 9 + c;
    }

    // prologue: stages 0..2
#pragma unroll
    for (int j = 0; j < 3; j++) {
#pragma unroll
        for (int m = 0; m < 2; m++)
            cp_async16(&wt4[(j & 3) * G2_WT4 + sslot[m]], W4 + gbase[m] + j * 8);
        asm volatile("cp.async.commit_group;");
    }

    float2 acc[8][2];
#pragma unroll
    for (int u = 0; u < 8; u++) { acc[u][0] = make_float2(0.f,0.f); acc[u][1] = make_float2(0.f,0.f); }

#pragma unroll 1
    for (int j = 0; j < 16; j++) {
        asm volatile("cp.async.wait_group 2;" ::: "memory");
        __syncthreads();
        if (j + 3 < 16) {
#pragma unroll
            for (int m = 0; m < 2; m++)
                cp_async16(&wt4[((j + 3) & 3) * G2_WT4 + sslot[m]], W4 + gbase[m] + (j + 3) * 8);
        }
        // ALWAYS commit (possibly empty group) so the drain count stays uniform.
        asm volatile("cp.async.commit_group;");
        // h for this j: 4 float4 (kk 0..3), batches 4*rsub..+3
        float4 hh[4];
#pragma unroll
        for (int kk = 0; kk < 4; kk++)
            hh[kk] = hs4[(8 * j + c4) * 17 + kk * 4 + rsub];
        const float4* wt = &wt4[(j & 3) * G2_WT4];
#pragma unroll
        for (int u = 0; u < 8; u++) {
            float4 w = wt[(warp * 8 + u) * 9 + c4];
            dfma2(acc[u][0], make_float2(w.x, w.x), make_float2(hh[0].x, hh[0].y));
            dfma2(acc[u][1], make_float2(w.x, w.x), make_float2(hh[0].z, hh[0].w));
            dfma2(acc[u][0], make_float2(w.y, w.y), make_float2(hh[1].x, hh[1].y));
            dfma2(acc[u][1], make_float2(w.y, w.y), make_float2(hh[1].z, hh[1].w));
            dfma2(acc[u][0], make_float2(w.z, w.z), make_float2(hh[2].x, hh[2].y));
            dfma2(acc[u][1], make_float2(w.z, w.z), make_float2(hh[2].z, hh[2].w));
            dfma2(acc[u][0], make_float2(w.w, w.w), make_float2(hh[3].x, hh[3].y));
            dfma2(acc[u][1], make_float2(w.w, w.w), make_float2(hh[3].z, hh[3].w));
        }
    }

    // reduce over c4 (lane bits 0..2)
#pragma unroll
    for (int m = 1; m <= 4; m <<= 1) {
#pragma unroll
        for (int u = 0; u < 8; u++) {
            acc[u][0].x += __shfl_xor_sync(0xffffffffu, acc[u][0].x, m);
            acc[u][0].y += __shfl_xor_sync(0xffffffffu, acc[u][0].y, m);
            acc[u][1].x += __shfl_xor_sync(0xffffffffu, acc[u][1].x, m);
            acc[u][1].y += __shfl_xor_sync(0xffffffffu, acc[u][1].y, m);
        }
    }

    if (c4 == 0) {
#pragma unroll
        for (int u = 0; u < 8; u++) {
            int r = row0 + warp * 8 + u;
            if (r < NROWS) {
                float bias = b2[r];
                int i = r & 1, rem = r >> 1;
                int c = rem / L0, l = rem - c * L0;
                float4 o;
                o.x = tanhf(acc[u][0].x + bias);
                o.y = tanhf(acc[u][0].y + bias);
                o.z = tanhf(acc[u][1].x + bias);
                o.w = tanhf(acc[u][1].y + bias);
                *(float4*)&g_a[(size_t)((i * CF + c) * L0 + l) * BATCH + 4 * rsub] = o;
            }
        }
    }
}

// ---------------- Stage 3: ConvT #0 (16->16) + tanh ----------------
__global__ __launch_bounds__(128) void k_conv0(
    const float* __restrict__ ctw0, const float* __restrict__ ctb0)
{
    int i   = blockIdx.y;
    int tid = threadIdx.x;
    __shared__ float ws[CF * CF * 33];
    for (int t = tid; t < CF * CF * KS; t += 128) {
        int ci = t >> 9, co = (t >> 5) & 15, k = t & 31;
        ws[(ci * 16 + co) * 33 + k] = ctw0[i * (CF * CF * KS) + t];
    }
    __syncthreads();

    int bp = tid & 7;
    int co = tid >> 3;
    int q0 = blockIdx.x * 4;

    float2 acc[4][4];
#pragma unroll
    for (int j = 0; j < 4; j++)
#pragma unroll
        for (int ph = 0; ph < 4; ph++) acc[j][ph] = make_float2(0.f, 0.f);

    float2 inv[2][11];
    {
        const float* src = g_a + (size_t)(i * CF * L0) * BATCH + 2 * bp;
#pragma unroll
        for (int t = 0; t < 11; t++) {
            int l = q0 - 3 + t;
            inv[0][t] = (l >= 0 && l <= L0 - 1) ? *(const float2*)(src + (size_t)l * BATCH)
                                                : make_float2(0.f, 0.f);
        }
    }

#pragma unroll
    for (int ci = 0; ci < CF; ci++) {
        int cur = ci & 1;
        if (ci + 1 < CF) {
            const float* src = g_a + (size_t)((i * CF + ci + 1) * L0) * BATCH + 2 * bp;
#pragma unroll
            for (int t = 0; t < 11; t++) {
                int l = q0 - 3 + t;
                inv[cur ^ 1][t] = (l >= 0 && l <= L0 - 1)
                    ? *(const float2*)(src + (size_t)l * BATCH) : make_float2(0.f, 0.f);
            }
        }
        const float* wsp = &ws[(ci * 16 + co) * 33];
#pragma unroll
        for (int s = 0; s < 8; s++)
#pragma unroll
            for (int ph = 0; ph < 4; ph++) {
                float wv = wsp[ph + 4 * s];
                float2 w2 = make_float2(wv, wv);
#pragma unroll
                for (int j = 0; j < 4; j++) dfma2(acc[j][ph], w2, inv[cur][j + 7 - s]);
            }
    }

    float bias = ctb0[i * CF + co];
#pragma unroll
    for (int j = 0; j < 4; j++)
#pragma unroll
        for (int ph = 0; ph < 4; ph++) {
            int o = 4 * (q0 + j) + ph;
            if (o < L1OUT) {
                float2 v;
                v.x = tanhf(acc[j][ph].x + bias);
                v.y = tanhf(acc[j][ph].y + bias);
                *(float2*)&g_c0[(size_t)((i * CF + co) * L1OUT + o) * BATCH + 2 * bp] = v;
            }
        }
}

// ---------------- Stage 4: ConvT #1 (16->1) + tanh, smem-staged ----------------
// Block 128 = 16 qi x 8 bp, 32 q per block. Input slab staged per ci.
__global__ __launch_bounds__(128) void k_conv1(
    const float* __restrict__ ctw1, const float* __restrict__ ctb1)
{
    __shared__ float  wv[CF * KS];
    __shared__ float2 tile[2][40 * 9];
    int i   = blockIdx.y;
    int tid = threadIdx.x;
    for (int t = tid; t < CF * KS; t += 128) wv[t] = ctw1[i * (CF * KS) + t];

    int bp = tid & 7;
    int qi = tid >> 3;
    int q0 = blockIdx.x * 32;
    int lbase = q0 - 3;

    // staging map: e = tid + 128m, e<320: lloc = e>>3, b = e&7
    int sl[3], sv[3], ss[3];
#pragma unroll
    for (int m = 0; m < 3; m++) {
        int e = tid + 128 * m;
        int lloc = e >> 3;
        int l = lbase + lloc;
        sl[m] = l * 8 + (e & 7);
        sv[m] = (e < 320) && (l >= 0) && (l <= L1OUT - 1);
        ss[m] = lloc * 9 + (e & 7);
    }

    float2 pf[3];
    {
        const float2* src = (const float2*)g_c0 + (size_t)(i * CF) * L1OUT * 8;
#pragma unroll
        for (int m = 0; m < 3; m++)
            pf[m] = sv[m] ? src[sl[m]] : make_float2(0.f, 0.f);
#pragma unroll
        for (int m = 0; m < 3; m++)
            if (tid + 128 * m < 320) tile[0][ss[m]] = pf[m];
    }
    __syncthreads();

    float2 acc[2][4];
#pragma unroll
    for (int j = 0; j < 2; j++)
#pragma unroll
        for (int ph = 0; ph < 4; ph++) acc[j][ph] = make_float2(0.f, 0.f);

#pragma unroll 1
    for (int ci = 0; ci < CF; ci++) {
        if (ci + 1 < CF) {
            const float2* src = (const float2*)g_c0 + (size_t)(i * CF + ci + 1) * L1OUT * 8;
#pragma unroll
            for (int m = 0; m < 3; m++)
                pf[m] = sv[m] ? src[sl[m]] : make_float2(0.f, 0.f);
        }
        const float2* tp = tile[ci & 1];
        float2 inv[9];
#pragma unroll
        for (int t = 0; t < 9; t++) inv[t] = tp[(2 * qi + t) * 9 + bp];
        const float* wp = &wv[ci * 32];
#pragma unroll
        for (int s = 0; s < 8; s++)
#pragma unroll
            for (int ph = 0; ph < 4; ph++) {
                float2 w2 = make_float2(wp[ph + 4 * s], wp[ph + 4 * s]);
                dfma2(acc[0][ph], w2, inv[7 - s]);
                dfma2(acc[1][ph], w2, inv[8 - s]);
            }
        if (ci + 1 < CF) {
            float2* tn = tile[(ci + 1) & 1];
#pragma unroll
            for (int m = 0; m < 3; m++)
                if (tid + 128 * m < 320) tn[ss[m]] = pf[m];
        }
        __syncthreads();
    }

    float bias = ctb1[i];
    int q = q0 + 2 * qi;
#pragma unroll
    for (int j = 0; j < 2; j++)
#pragma unroll
        for (int ph = 0; ph < 4; ph++) {
            int o = 4 * (q + j) + ph;
            float2 v;
            v.x = tanhf(acc[j][ph].x + bias);
            v.y = tanhf(acc[j][ph].y + bias);
            *(float2*)&g_c1[(size_t)(i * N_NODES + o) * BATCH + 2 * bp] = v;
        }
}

// ---------------- Stage 5: gather + combine ----------------
__global__ __launch_bounds__(256) void k_gather(
    const float* __restrict__ sps_w, const float* __restrict__ sps_b,
    const float* __restrict__ final_w, const float* __restrict__ final_b,
    const float* __restrict__ out_w, const float* __restrict__ out_b,
    const int* __restrict__ ord, float* __restrict__ out)
{
    __shared__ float gs[SFC][258][17];
    int tid = threadIdx.x;
    int n0  = blockIdx.x * 256;

    for (int t = tid; t < SFC * 258; t += 256) {
        int i  = (t >= 258);
        int tt = t - i * 258;
        int n  = n0 - 1 + tt;
        n = n < 0 ? 0 : (n > N_NODES - 1 ? N_NODES - 1 : n);
        int idx = ord[i * N_NODES + n];
        const float4* s4 = (const float4*)&g_c1[(size_t)(i * N_NODES + idx) * BATCH];
        float tmp[16];
        *(float4*)&tmp[0]  = s4[0];
        *(float4*)&tmp[4]  = s4[1];
        *(float4*)&tmp[8]  = s4[2];
        *(float4*)&tmp[12] = s4[3];
        float* row = gs[i][tt];
#pragma unroll
        for (int b = 0; b < 16; b++) row[b] = tmp[b];
    }
    __syncthreads();

    int n = n0 + tid;
    float w[SFC][3], sb[SFC];
#pragma unroll
    for (int i = 0; i < SFC; i++) {
        const float* wp = &sps_w[(size_t)(i * N_NODES + n) * 3];
        w[i][0] = wp[0]; w[i][1] = wp[1]; w[i][2] = wp[2];
        sb[i] = sps_b[i * N_NODES + n];
    }
    float fw0 = final_w[2 * n], fw1 = final_w[2 * n + 1];
    float fb = final_b[n], ow = out_w[n], ob = out_b[n];

#pragma unroll
    for (int b = 0; b < BATCH; b++) {
        float z0 = tanhf(gs[0][tid][b] * w[0][0] + gs[0][tid + 1][b] * w[0][1]
                       + gs[0][tid + 2][b] * w[0][2] + sb[0]);
        float z1 = tanhf(gs[1][tid][b] * w[1][0] + gs[1][tid + 1][b] * w[1][1]
                       + gs[1][tid + 2][b] * w[1][2] + sb[1]);
        float zz = tanhf(z0 * fw0 + z1 * fw1 + fb);
        out[(size_t)b * N_NODES + n] = zz * ow + ob;
    }
}

// ---------------- launch ----------------
extern "C" void kernel_launch(void* const* d_in, const int* in_sizes, int n_in,
                              void* d_out, int out_size)
{
    const float* x       = (const float*)d_in[0];
    const float* W1      = (const float*)d_in[1];
    const float* b1      = (const float*)d_in[2];
    const float* W2      = (const float*)d_in[3];
    const float* b2      = (const float*)d_in[4];
    const float* ctw0    = (const float*)d_in[5];
    const float* ctb0    = (const float*)d_in[6];
    const float* ctw1    = (const float*)d_in[7];
    const float* ctb1    = (const float*)d_in[8];
    const float* sps_w   = (const float*)d_in[9];
    const float* sps_b   = (const float*)d_in[10];
    const float* final_w = (const float*)d_in[11];
    const float* final_b = (const float*)d_in[12];
    const float* out_w   = (const float*)d_in[13];
    const float* out_b   = (const float*)d_in[14];
    const int*   ord     = (const int*)d_in[15];
    float* out = (float*)d_out;

    static int smem_set = 0;
    if (!smem_set) {
        cudaFuncSetAttribute(k_gemm2, cudaFuncAttributeMaxDynamicSharedMemorySize,
                             G2_SMEM);
        smem_set = 1;
    }

    k_gemm1<<<32, 256>>>(x, W1, b1);
    k_gemm2<<<(NROWS + 63) / 64, 256, G2_SMEM>>>(W2, b2);
    k_conv0<<<dim3(1025, SFC), 128>>>(ctw0, ctb0);
    k_conv1<<<dim3(512, SFC), 128>>>(ctw1, ctb1);
    k_gather<<<dim3(256, 1), 256>>>(sps_w, sps_b, final_w, final_b,
                                    out_w, out_b, ord, out);
}